// round 9
// baseline (speedup 1.0000x reference)
#include <cuda_runtime.h>
#include <cuda_fp16.h>
#include <cstdint>

#define DIM 1536
#define NH 12
#define HD 128
#define S_MAX 4680

// ---------------- scratch ----------------
__device__ float  g_qraw[S_MAX * DIM];   // later: attn split-0 partial o
__device__ float  g_kraw[S_MAX * DIM];   // later: attn split-1 partial o
__device__ float  g_att[S_MAX * DIM];
__device__ float  g_ml[2 * S_MAX * NH * 2];
__device__ __half g_xh[S_MAX * DIM];
__device__ __half g_vh[S_MAX * DIM];
__device__ __half g_atth[S_MAX * DIM];
__device__ __half g_rq[S_MAX * DIM];
__device__ __half g_rk[S_MAX * DIM];
__device__ __half g_wqh[DIM * DIM];
__device__ __half g_wkh[DIM * DIM];
__device__ __half g_wvh[DIM * DIM];
__device__ __half g_woh[DIM * DIM];
__device__ float  g_rope[S_MAX * HD];
__device__ float  g_z[S_MAX * NH];
__device__ __half g_Mh[NH * HD * HD];   // [n][j][d] fp16

// ---------------- helpers ----------------
__device__ __forceinline__ uint32_t smaddr(const void* p) {
    return (uint32_t)__cvta_generic_to_shared(p);
}
__device__ __forceinline__ void ldsm4(uint32_t* r, uint32_t a) {
    asm volatile("ldmatrix.sync.aligned.m8n8.x4.shared.b16 {%0,%1,%2,%3},[%4];"
                 : "=r"(r[0]), "=r"(r[1]), "=r"(r[2]), "=r"(r[3]) : "r"(a));
}
__device__ __forceinline__ void ldsm4t(uint32_t* r, uint32_t a) {
    asm volatile("ldmatrix.sync.aligned.m8n8.x4.trans.shared.b16 {%0,%1,%2,%3},[%4];"
                 : "=r"(r[0]), "=r"(r[1]), "=r"(r[2]), "=r"(r[3]) : "r"(a));
}
__device__ __forceinline__ void mma16(float* c, const uint32_t* a, uint32_t b0, uint32_t b1) {
    asm volatile(
        "mma.sync.aligned.m16n8k16.row.col.f32.f16.f16.f32 "
        "{%0,%1,%2,%3},{%4,%5,%6,%7},{%8,%9},{%0,%1,%2,%3};\n"
        : "+f"(c[0]), "+f"(c[1]), "+f"(c[2]), "+f"(c[3])
        : "r"(a[0]), "r"(a[1]), "r"(a[2]), "r"(a[3]), "r"(b0), "r"(b1));
}
__device__ __forceinline__ uint32_t packh2(float x, float y) {
    __half2 h = __floats2half2_rn(x, y);
    return *reinterpret_cast<uint32_t*>(&h);
}
__device__ __forceinline__ void cpa16(uint32_t dst, const void* src, int sb) {
    asm volatile("cp.async.cg.shared.global [%0], [%1], 16, %2;" :: "r"(dst), "l"(src), "r"(sb));
}
#define CP_COMMIT() asm volatile("cp.async.commit_group;" ::: "memory")
#define CP_WAIT1()  asm volatile("cp.async.wait_group 1;" ::: "memory")
#define CP_WAIT2()  asm volatile("cp.async.wait_group 2;" ::: "memory")

// ---------------- fp32 -> fp16 convert ----------------
__global__ void conv_h(const float* __restrict__ src, __half* __restrict__ dst, int n4) {
    int i = blockIdx.x * 256 + threadIdx.x;
    if (i < n4) {
        float4 v = ((const float4*)src)[i];
        ((__half2*)dst)[2 * i]     = __floats2half2_rn(v.x, v.y);
        ((__half2*)dst)[2 * i + 1] = __floats2half2_rn(v.z, v.w);
    }
}

// ---------------- rope table ----------------
__global__ void rope_table_k(const float* __restrict__ freqs,
                             const int* __restrict__ hg, const int* __restrict__ wg) {
    int s = blockIdx.x;
    int i = threadIdx.x;
    int h = hg[0], w = wg[0];
    int hw = h * w;
    int fi = s / hw;
    int rem = s - fi * hw;
    int hi = rem / w;
    int wi = rem - hi * w;
    int r = (i < 22) ? fi : ((i < 43) ? hi : wi);
    float2 v = ((const float2*)freqs)[r * 64 + i];
    ((float2*)g_rope)[s * 64 + i] = v;
}

// ---------------- fused QKV NT GEMM (3-stage cp.async) ----------------
#define GEMM_SMEM_BYTES (6 * 128 * 64 * 2)  // 96KB

__global__ __launch_bounds__(256, 2) void gemm_qkv(const __half* __restrict__ A,
                                                   const __half* __restrict__ Bq,
                                                   const __half* __restrict__ Bk,
                                                   const __half* __restrict__ Bv,
                                                   const float* __restrict__ bq,
                                                   const float* __restrict__ bk,
                                                   const float* __restrict__ bv,
                                                   float* __restrict__ Cq,
                                                   float* __restrict__ Ck,
                                                   __half* __restrict__ Cv, int M) {
    extern __shared__ __align__(16) __half gsm[];
    __half* As = gsm;
    __half* Bs = gsm + 3 * 128 * 64;
    const uint32_t asb = smaddr(As), bsb = smaddr(Bs);
    const int tid = threadIdx.x, lane = tid & 31, warp = tid >> 5;
    const int wm = warp >> 2, wn = warp & 3, q = lane & 3, g2 = lane >> 2;
    const int quad = lane >> 3, l7 = lane & 7;
    const int mbase = blockIdx.x * 128;
    const int mat = blockIdx.y / 12;
    const int nbase = (blockIdx.y % 12) * 128;
    const __half* B = (mat == 0) ? Bq : (mat == 1) ? Bk : Bv;
    const float* bias = (mat == 0) ? bq : (mat == 1) ? bk : bv;
    const int NK = DIM / 64;  // 24

    float acc[4][4][4];
#pragma unroll
    for (int i = 0; i < 4; i++)
#pragma unroll
        for (int j = 0; j < 4; j++)
#pragma unroll
            for (int k = 0; k < 4; k++) acc[i][j][k] = 0.f;

    auto issue = [&](int s) {
        if (s < NK) {
            int k0 = s * 64;
            int st = s % 3;
            uint32_t ad = asb + st * 16384;
            uint32_t bd = bsb + st * 16384;
#pragma unroll
            for (int it = 0; it < 4; it++) {
                int idx = tid + it * 256;
                int r = idx >> 3, c = idx & 7;
                int off = r * 128 + ((c ^ (r & 7)) << 4);
                int arow = mbase + r;
                int ar = arow < M ? arow : M - 1;
                cpa16(ad + off, A + (size_t)ar * DIM + k0 + c * 8, arow < M ? 16 : 0);
                cpa16(bd + off, B + (size_t)(nbase + r) * DIM + k0 + c * 8, 16);
            }
        }
        CP_COMMIT();
    };

    issue(0); issue(1); issue(2);

    for (int kt = 0; kt < NK; kt++) {
        CP_WAIT2();
        __syncthreads();
        int st = kt % 3;
        uint32_t ab = asb + st * 16384;
        uint32_t bb = bsb + st * 16384;
#pragma unroll
        for (int ks = 0; ks < 4; ks++) {
            uint32_t af[4][4];
#pragma unroll
            for (int mt = 0; mt < 4; mt++) {
                int row = wm * 64 + mt * 16 + ((quad & 1) << 3) + l7;
                int c = ks * 2 + (quad >> 1);
                ldsm4(af[mt], ab + row * 128 + ((c ^ (row & 7)) << 4));
            }
#pragma unroll
            for (int nb = 0; nb < 2; nb++) {
                uint32_t bf[4];
                int n = wn * 32 + nb * 16 + ((quad >> 1) << 3) + l7;
                int c = ks * 2 + (quad & 1);
                ldsm4(bf, bb + n * 128 + ((c ^ (n & 7)) << 4));
#pragma unroll
                for (int mt = 0; mt < 4; mt++) {
                    mma16(acc[mt][nb * 2], af[mt], bf[0], bf[1]);
                    mma16(acc[mt][nb * 2 + 1], af[mt], bf[2], bf[3]);
                }
            }
        }
        __syncthreads();
        issue(kt + 3);
    }
#pragma unroll
    for (int mt = 0; mt < 4; mt++) {
        int r0 = mbase + wm * 64 + mt * 16 + g2;
#pragma unroll
        for (int nt = 0; nt < 4; nt++) {
            int c0 = nbase + wn * 32 + nt * 8 + 2 * q;
            float v0 = acc[mt][nt][0] + bias[c0];
            float v1 = acc[mt][nt][1] + bias[c0 + 1];
            float v2 = acc[mt][nt][2] + bias[c0];
            float v3 = acc[mt][nt][3] + bias[c0 + 1];
            if (mat == 2) {
                if (r0 < M)
                    *(__half2*)(Cv + (size_t)r0 * DIM + c0) = __floats2half2_rn(v0, v1);
                if (r0 + 8 < M)
                    *(__half2*)(Cv + (size_t)(r0 + 8) * DIM + c0) = __floats2half2_rn(v2, v3);
            } else {
                float* C = (mat == 0) ? Cq : Ck;
                if (r0 < M) {
                    C[(size_t)r0 * DIM + c0] = v0;
                    C[(size_t)r0 * DIM + c0 + 1] = v1;
                }
                if (r0 + 8 < M) {
                    C[(size_t)(r0 + 8) * DIM + c0] = v2;
                    C[(size_t)(r0 + 8) * DIM + c0 + 1] = v3;
                }
            }
        }
    }
}

// ---------------- single NT GEMM (Wo), 3-stage ----------------
__global__ __launch_bounds__(256, 2) void gemm_h(const __half* __restrict__ A,
                                                 const __half* __restrict__ B,
                                                 const float* __restrict__ bias,
                                                 float* __restrict__ C, int M) {
    extern __shared__ __align__(16) __half gsm[];
    __half* As = gsm;
    __half* Bs = gsm + 3 * 128 * 64;
    const uint32_t asb = smaddr(As), bsb = smaddr(Bs);
    const int tid = threadIdx.x, lane = tid & 31, warp = tid >> 5;
    const int wm = warp >> 2, wn = warp & 3, q = lane & 3, g2 = lane >> 2;
    const int quad = lane >> 3, l7 = lane & 7;
    const int mbase = blockIdx.x * 128, nbase = blockIdx.y * 128;
    const int NK = DIM / 64;

    float acc[4][4][4];
#pragma unroll
    for (int i = 0; i < 4; i++)
#pragma unroll
        for (int j = 0; j < 4; j++)
#pragma unroll
            for (int k = 0; k < 4; k++) acc[i][j][k] = 0.f;

    auto issue = [&](int s) {
        if (s < NK) {
            int k0 = s * 64;
            int st = s % 3;
            uint32_t ad = asb + st * 16384;
            uint32_t bd = bsb + st * 16384;
#pragma unroll
            for (int it = 0; it < 4; it++) {
                int idx = tid + it * 256;
                int r = idx >> 3, c = idx & 7;
                int off = r * 128 + ((c ^ (r & 7)) << 4);
                int arow = mbase + r;
                int ar = arow < M ? arow : M - 1;
                cpa16(ad + off, A + (size_t)ar * DIM + k0 + c * 8, arow < M ? 16 : 0);
                cpa16(bd + off, B + (size_t)(nbase + r) * DIM + k0 + c * 8, 16);
            }
        }
        CP_COMMIT();
    };

    issue(0); issue(1); issue(2);

    for (int kt = 0; kt < NK; kt++) {
        CP_WAIT2();
        __syncthreads();
        int st = kt % 3;
        uint32_t ab = asb + st * 16384;
        uint32_t bb = bsb + st * 16384;
#pragma unroll
        for (int ks = 0; ks < 4; ks++) {
            uint32_t af[4][4];
#pragma unroll
            for (int mt = 0; mt < 4; mt++) {
                int row = wm * 64 + mt * 16 + ((quad & 1) << 3) + l7;
                int c = ks * 2 + (quad >> 1);
                ldsm4(af[mt], ab + row * 128 + ((c ^ (row & 7)) << 4));
            }
#pragma unroll
            for (int nb = 0; nb < 2; nb++) {
                uint32_t bf[4];
                int n = wn * 32 + nb * 16 + ((quad >> 1) << 3) + l7;
                int c = ks * 2 + (quad & 1);
                ldsm4(bf, bb + n * 128 + ((c ^ (n & 7)) << 4));
#pragma unroll
                for (int mt = 0; mt < 4; mt++) {
                    mma16(acc[mt][nb * 2], af[mt], bf[0], bf[1]);
                    mma16(acc[mt][nb * 2 + 1], af[mt], bf[2], bf[3]);
                }
            }
        }
        __syncthreads();
        issue(kt + 3);
    }
#pragma unroll
    for (int mt = 0; mt < 4; mt++) {
        int r0 = mbase + wm * 64 + mt * 16 + g2;
#pragma unroll
        for (int nt = 0; nt < 4; nt++) {
            int c0 = nbase + wn * 32 + nt * 8 + 2 * q;
            if (r0 < M) {
                C[(size_t)r0 * DIM + c0]     = acc[mt][nt][0] + bias[c0];
                C[(size_t)r0 * DIM + c0 + 1] = acc[mt][nt][1] + bias[c0 + 1];
            }
            if (r0 + 8 < M) {
                C[(size_t)(r0 + 8) * DIM + c0]     = acc[mt][nt][2] + bias[c0];
                C[(size_t)(r0 + 8) * DIM + c0 + 1] = acc[mt][nt][3] + bias[c0 + 1];
            }
        }
    }
}

// ---------------- RMS + RoPE + optional z ----------------
__global__ __launch_bounds__(384) void rmsrope_k(const float* __restrict__ in,
                                                 const float* __restrict__ g,
                                                 const float* __restrict__ gkm,
                                                 __half* __restrict__ out,
                                                 float* __restrict__ zout, int doZ,
                                                 float prescale) {
    const int s = blockIdx.x;
    const int t = threadIdx.x;
    const int warp = t >> 5, lane = t & 31;
    float4 v = ((const float4*)(in + (size_t)s * DIM))[t];
    float ss = v.x * v.x + v.y * v.y + v.z * v.z + v.w * v.w;
#pragma unroll
    for (int off = 16; off; off >>= 1) ss += __shfl_xor_sync(~0u, ss, off);
    __shared__ float red[12];
    __shared__ float sinv;
    if (lane == 0) red[warp] = ss;
    __syncthreads();
    if (t == 0) {
        float tot = 0;
#pragma unroll
        for (int i = 0; i < 12; i++) tot += red[i];
        sinv = rsqrtf(tot * (1.0f / DIM) + 1e-6f);
    }
    __syncthreads();
    const float inv = sinv;
    const int e = t * 4;
    float y0 = v.x * inv * g[e + 0];
    float y1 = v.y * inv * g[e + 1];
    float y2 = v.z * inv * g[e + 2];
    float y3 = v.w * inv * g[e + 3];
    if (doZ) {
        float zp = fmaxf(y0, 0.f) * gkm[e + 0] + fmaxf(y1, 0.f) * gkm[e + 1] +
                   fmaxf(y2, 0.f) * gkm[e + 2] + fmaxf(y3, 0.f) * gkm[e + 3];
#pragma unroll
        for (int off = 16; off; off >>= 1) zp += __shfl_xor_sync(~0u, zp, off);
        if (lane == 0) zout[s * NH + warp] = 1.0f / (zp + 1e-6f);
    }
    const int i0 = (2 * t) & 63;
    const float* rp = g_rope + (size_t)s * HD + i0 * 2;
    float c0 = rp[0], s0 = rp[1], c1 = rp[2], s1 = rp[3];
    float o0 = (y0 * c0 - y1 * s0) * prescale;
    float o1 = (y0 * s0 + y1 * c0) * prescale;
    float o2 = (y2 * c1 - y3 * s1) * prescale;
    float o3 = (y2 * s1 + y3 * c1) * prescale;
    __half2* op = (__half2*)(out + (size_t)s * DIM);
    op[t * 2]     = __floats2half2_rn(o0, o1);
    op[t * 2 + 1] = __floats2half2_rn(o2, o3);
}

// ---------------- split-KV fp16 flash attention ----------------
#define KS_BYTES 16384
#define ATT_SMEM_BYTES ((128 * 128 + 4 * 64 * 128) * 2)  // 96KB

__global__ __launch_bounds__(256, 2) void attn_f16(const __half* __restrict__ RQ,
                                                   const __half* __restrict__ RK,
                                                   const __half* __restrict__ V,
                                                   float* __restrict__ O0,
                                                   float* __restrict__ O1,
                                                   float* __restrict__ ML, int S) {
    extern __shared__ __align__(16) __half smh[];
    __half* Qs = smh;
    __half* Ks = smh + 128 * 128;
    __half* Vs = smh + 128 * 128 + 2 * 64 * 128;
    const uint32_t qsb = smaddr(Qs), ksb = smaddr(Ks), vsb = smaddr(Vs);
    const int tid = threadIdx.x, lane = tid & 31, warp = tid >> 5;
    const int q = lane & 3, g2 = lane >> 2, quad = lane >> 3, l7 = lane & 7;
    const int head = blockIdx.y;
    const int split = blockIdx.z;
    const int qbase = blockIdx.x * 128;
    const int nkt = (S + 63) >> 6;
    const int nspl = (nkt + 1) >> 1;
    const int ktlo = split * nspl;
    const int kthi = min(nkt, ktlo + nspl);
    float* O = split ? O1 : O0;

    // Q tile
#pragma unroll
    for (int it = 0; it < 8; it++) {
        int idx = tid + it * 256;
        int r = idx >> 4, c = idx & 15;
        uint4 v = make_uint4(0, 0, 0, 0);
        if (qbase + r < S) v = *(const uint4*)(RQ + (size_t)(qbase + r) * DIM + head * HD + c * 8);
        int cp = (c & 8) | ((c ^ (r & 7)) & 7);
        *(uint4*)((char*)Qs + r * 256 + (cp << 4)) = v;
    }

    auto issue = [&](int s) {
        if (s < kthi) {
            int kb = s * 64;
            uint32_t kd = ksb + (s & 1) * KS_BYTES;
            uint32_t vd = vsb + (s & 1) * KS_BYTES;
#pragma unroll
            for (int it = 0; it < 4; it++) {
                int idx = tid + it * 256;
                int r = idx >> 4, c = idx & 15;
                int row = kb + r;
                int rc = row < S ? row : S - 1;
                int sb = row < S ? 16 : 0;
                int cp = (c & 8) | ((c ^ (r & 7)) & 7);
                int off = r * 256 + (cp << 4);
                const size_t go = (size_t)rc * DIM + head * HD + c * 8;
                cpa16(kd + off, RK + go, sb);
                cpa16(vd + off, V + go, sb);
            }
        }
        CP_COMMIT();
    };
    issue(ktlo);
    issue(ktlo + 1);
    __syncthreads();

    float o[16][4];
    float mrow[2], lrow[2];
#pragma unroll
    for (int i = 0; i < 16; i++)
#pragma unroll
        for (int j = 0; j < 4; j++) o[i][j] = 0.f;
    mrow[0] = mrow[1] = -1e30f;
    lrow[0] = lrow[1] = 0.f;

    for (int kt = ktlo; kt < kthi; kt++) {
        const int kb = kt * 64;
        CP_WAIT1();
        __syncthreads();
        const uint32_t kbb = ksb + (kt & 1) * KS_BYTES;
        const uint32_t vbb = vsb + (kt & 1) * KS_BYTES;

        // QK^T (log2-domain)
        float sc[8][4];
#pragma unroll
        for (int nt = 0; nt < 8; nt++)
#pragma unroll
            for (int j = 0; j < 4; j++) sc[nt][j] = 0.f;
#pragma unroll
        for (int ks = 0; ks < 8; ks++) {
            uint32_t af[4];
            {
                int row = warp * 16 + ((quad & 1) << 3) + l7;
                int c = ks * 2 + (quad >> 1);
                int cp = (c & 8) | ((c ^ (row & 7)) & 7);
                ldsm4(af, qsb + row * 256 + (cp << 4));
            }
#pragma unroll
            for (int nb = 0; nb < 4; nb++) {
                uint32_t bf[4];
                int n = nb * 16 + ((quad >> 1) << 3) + l7;
                int c = ks * 2 + (quad & 1);
                int cp = (c & 8) | ((c ^ (n & 7)) & 7);
                ldsm4(bf, kbb + n * 256 + (cp << 4));
                mma16(sc[nb * 2], af, bf[0], bf[1]);
                mma16(sc[nb * 2 + 1], af, bf[2], bf[3]);
            }
        }
        // online softmax (exp2)
        float fct[2];
#pragma unroll
        for (int hf = 0; hf < 2; hf++) {
            float tm = -1e30f;
#pragma unroll
            for (int nt = 0; nt < 8; nt++)
#pragma unroll
                for (int j = 0; j < 2; j++) {
                    int col = kb + nt * 8 + 2 * q + j;
                    float v = (col < S) ? sc[nt][hf * 2 + j] : -1e30f;
                    sc[nt][hf * 2 + j] = v;
                    tm = fmaxf(tm, v);
                }
            tm = fmaxf(tm, __shfl_xor_sync(~0u, tm, 1));
            tm = fmaxf(tm, __shfl_xor_sync(~0u, tm, 2));
            float mn = fmaxf(mrow[hf], tm);
            fct[hf] = exp2f(mrow[hf] - mn);
            mrow[hf] = mn;
            float rs = 0.f;
#pragma unroll
            for (int nt = 0; nt < 8; nt++)
#pragma unroll
                for (int j = 0; j < 2; j++) {
                    float p = exp2f(sc[nt][hf * 2 + j] - mn);
                    sc[nt][hf * 2 + j] = p;
                    rs += p;
                }
            rs += __shfl_xor_sync(~0u, rs, 1);
            rs += __shfl_xor_sync(~0u, rs, 2);
            lrow[hf] = lrow[hf] * fct[hf] + rs;
        }
        if (__ballot_sync(0xffffffffu, (fct[0] != 1.f) || (fct[1] != 1.f))) {
#pragma unroll
            for (int nt = 0; nt < 16; nt++) {
                o[nt][0] *= fct[0];
                o[nt][1] *= fct[0];
                o[nt][2] *= fct[1];
                o[nt][3] *= fct[1];
            }
        }
        // P @ V
#pragma unroll
        for (int ks = 0; ks < 4; ks++) {
            uint32_t af[4];
            af[0] = packh2(sc[2 * ks][0],     sc[2 * ks][1]);
            af[1] = packh2(sc[2 * ks][2],     sc[2 * ks][3]);
            af[2] = packh2(sc[2 * ks + 1][0], sc[2 * ks + 1][1]);
            af[3] = packh2(sc[2 * ks + 1][2], sc[2 * ks + 1][3]);
#pragma unroll
            for (int nb = 0; nb < 8; nb++) {
                uint32_t bf[4];
                int row = ks * 16 + ((quad & 1) << 3) + l7;
                int c = nb * 2 + (quad >> 1);
                int cp = (c & 8) | ((c ^ (row & 7)) & 7);
                ldsm4t(bf, vbb + row * 256 + (cp << 4));
                mma16(o[nb * 2], af, bf[0], bf[1]);
                mma16(o[nb * 2 + 1], af, bf[2], bf[3]);
            }
        }
        __syncthreads();
        issue(kt + 2);
    }
    // epilogue: unnormalized o + (m,l)
    const int r0 = warp * 16 + g2;
#pragma unroll
    for (int hf = 0; hf < 2; hf++) {
        int r = qbase + r0 + hf * 8;
        if (r < S) {
#pragma unroll
            for (int nt = 0; nt < 16; nt++) {
                O[(size_t)r * DIM + head * HD + nt * 8 + 2 * q]     = o[nt][hf * 2];
                O[(size_t)r * DIM + head * HD + nt * 8 + 2 * q + 1] = o[nt][hf * 2 + 1];
            }
            if (q == 0) {
                size_t mi = (((size_t)split * S + r) * NH + head) * 2;
                ML[mi]     = mrow[hf];
                ML[mi + 1] = lrow[hf];
            }
        }
    }
}

// ---------------- combine split softmaxes ----------------
__global__ __launch_bounds__(384) void combine_k(const float* __restrict__ o0,
                                                 const float* __restrict__ o1,
                                                 const float* __restrict__ ml,
                                                 float* __restrict__ att, int S) {
    const int s = blockIdx.x;
    const int t = threadIdx.x;
    const int head = t >> 5, lane = t & 31;
    size_t mi0 = (((size_t)0 * S + s) * NH + head) * 2;
    size_t mi1 = (((size_t)1 * S + s) * NH + head) * 2;
    float m0 = ml[mi0], l0 = ml[mi0 + 1];
    float m1 = ml[mi1], l1 = ml[mi1 + 1];
    float m = fmaxf(m0, m1);
    float w0 = exp2f(m0 - m), w1 = exp2f(m1 - m);
    float inv = 1.0f / (w0 * l0 + w1 * l1);
    size_t base = (size_t)s * DIM + head * HD + lane * 4;
    float4 a = *(const float4*)(o0 + base);
    float4 b = *(const float4*)(o1 + base);
    float4 r;
    r.x = (a.x * w0 + b.x * w1) * inv;
    r.y = (a.y * w0 + b.y * w1) * inv;
    r.z = (a.z * w0 + b.z * w1) * inv;
    r.w = (a.w * w0 + b.w * w1) * inv;
    *(float4*)(att + base) = r;
}

// ---------------- Mh[n][j][d] = half( sum_m g_kv[n,d,m] * Wlin[j,m] ) ----------------
__global__ __launch_bounds__(256) void prepM_k(const float* __restrict__ g_kv,
                                               const float* __restrict__ Wlin) {
    int o = blockIdx.x * 256 + threadIdx.x;
    int n = o >> 14;
    int j = (o >> 7) & 127;
    int d = o & 127;
    const float* gp = g_kv + ((size_t)n * 128 + d) * 128;
    const float* wp = Wlin + (size_t)j * 128;
    float acc = 0.f;
#pragma unroll 8
    for (int mm = 0; mm < 128; mm++) acc += gp[mm] * wp[mm];
    g_Mh[o] = __float2half(acc);
}

// ---------------- gated MMA: atth = half(att + z*(rq @ Mh_n^T) + blin) ----------------
#define GATED_SMEM_BYTES (2 * 128 * 128 * 2)

__global__ __launch_bounds__(256, 2) void gatedmma_k(const __half* __restrict__ RQ,
                                                     const __half* __restrict__ Mh,
                                                     const float* __restrict__ blin,
                                                     const float* __restrict__ att,
                                                     const float* __restrict__ zbuf,
                                                     __half* __restrict__ atth, int S) {
    extern __shared__ __align__(16) __half gsm2[];
    __half* As = gsm2;
    __half* Bs = gsm2 + 128 * 128;
    const uint32_t asb = smaddr(As), bsb = smaddr(Bs);
    const int tid = threadIdx.x, lane = tid & 31, warp = tid >> 5;
    const int wm = warp >> 2, wn = warp & 3, q = lane & 3, g2 = lane >> 2;
    const int quad = lane >> 3, l7 = lane & 7;
    const int head = blockIdx.y;
    const int qbase = blockIdx.x * 128;

#pragma unroll
    for (int it = 0; it < 8; it++) {
        int idx = tid + it * 256;
        int r = idx >> 4, c = idx & 15;
        int cp = (c & 8) | ((c ^ (r & 7)) & 7);
        uint4 va = make_uint4(0, 0, 0, 0);
        if (qbase + r < S) va = *(const uint4*)(RQ + (size_t)(qbase + r) * DIM + head * HD + c * 8);
        *(uint4*)((char*)As + r * 256 + (cp << 4)) = va;
        uint4 vb = *(const uint4*)(Mh + (size_t)head * HD * HD + r * HD + c * 8);
        *(uint4*)((char*)Bs + r * 256 + (cp << 4)) = vb;
    }
    __syncthreads();

    float acc[4][4][4];
#pragma unroll
    for (int i = 0; i < 4; i++)
#pragma unroll
        for (int j = 0; j < 4; j++)
#pragma unroll
            for (int k = 0; k < 4; k++) acc[i][j][k] = 0.f;

#pragma unroll
    for (int ks = 0; ks < 8; ks++) {
        uint32_t af[4][4];
#pragma unroll
        for (int mt = 0; mt < 4; mt++) {
            int row = wm * 64 + mt * 16 + ((quad & 1) << 3) + l7;
            int c = ks * 2 + (quad >> 1);
            int cp = (c & 8) | ((c ^ (row & 7)) & 7);
            ldsm4(af[mt], asb + row * 256 + (cp << 4));
        }
#pragma unroll
        for (int nb = 0; nb < 2; nb++) {
            uint32_t bf[4];
            int n = wn * 32 + nb * 16 + ((quad >> 1) << 3) + l7;
            int c = ks * 2 + (quad & 1);
            int cp = (c & 8) | ((c ^ (n & 7)) & 7);
            ldsm4(bf, bsb + n * 256 + (cp << 4));
#pragma unroll
            for (int mt = 0; mt < 4; mt++) {
                mma16(acc[mt][nb * 2], af[mt], bf[0], bf[1]);
                mma16(acc[mt][nb * 2 + 1], af[mt], bf[2], bf[3]);
            }
        }
    }
#pragma unroll
    for (int mt = 0; mt < 4; mt++) {
        int r0 = qbase + wm * 64 + mt * 16 + g2;
        float z0 = (r0 < S) ? zbuf[r0 * NH + head] : 0.f;
        float z1 = (r0 + 8 < S) ? zbuf[(r0 + 8) * NH + head] : 0.f;
#pragma unroll
        for (int nt = 0; nt < 4; nt++) {
            int c0 = wn * 32 + nt * 8 + 2 * q;
            float b0 = blin[c0], b1 = blin[c0 + 1];
            if (r0 < S) {
                size_t i0 = (size_t)r0 * DIM + head * HD + c0;
                *(__half2*)(atth + i0) = __floats2half2_rn(
                    att[i0] + acc[mt][nt][0] * z0 + b0,
                    att[i0 + 1] + acc[mt][nt][1] * z0 + b1);
            }
            if (r0 + 8 < S) {
                size_t i1 = (size_t)(r0 + 8) * DIM + head * HD + c0;
                *(__half2*)(atth + i1) = __floats2half2_rn(
                    att[i1] + acc[mt][nt][2] * z1 + b0,
                    att[i1 + 1] + acc[mt][nt][3] * z1 + b1);
            }
        }
    }
}

// ---------------- host ----------------
extern "C" void kernel_launch(void* const* d_in, const int* in_sizes, int n_in,
                              void* d_out, int out_size) {
    const float* x       = (const float*)d_in[0];
    const float* freqs   = (const float*)d_in[1];
    const float* g_kmean = (const float*)d_in[2];
    const float* g_kv    = (const float*)d_in[3];
    const float* Wq = (const float*)d_in[4];  const float* bq = (const float*)d_in[5];
    const float* Wk = (const float*)d_in[6];  const float* bk = (const float*)d_in[7];
    const float* Wv = (const float*)d_in[8];  const float* bv = (const float*)d_in[9];
    const float* Wo = (const float*)d_in[10]; const float* bo = (const float*)d_in[11];
    const float* gq = (const float*)d_in[12]; const float* gk = (const float*)d_in[13];
    const float* Wlin = (const float*)d_in[14]; const float* blin = (const float*)d_in[15];
    const int* hG = (const int*)d_in[17];
    const int* wG = (const int*)d_in[18];
    float* out = (float*)d_out;

    int S = in_sizes[0] / DIM;
    if (S > S_MAX) S = S_MAX;

    cudaFuncSetAttribute(attn_f16, cudaFuncAttributeMaxDynamicSharedMemorySize, ATT_SMEM_BYTES);
    cudaFuncSetAttribute(gemm_h, cudaFuncAttributeMaxDynamicSharedMemorySize, GEMM_SMEM_BYTES);
    cudaFuncSetAttribute(gemm_qkv, cudaFuncAttributeMaxDynamicSharedMemorySize, GEMM_SMEM_BYTES);
    cudaFuncSetAttribute(gatedmma_k, cudaFuncAttributeMaxDynamicSharedMemorySize, GATED_SMEM_BYTES);

    float *qraw, *kraw, *att, *zbuf, *mlbuf;
    __half *xh, *vh, *atth, *rq, *rk, *wqh, *wkh, *wvh, *woh, *mh;
    cudaGetSymbolAddress((void**)&qraw, g_qraw);
    cudaGetSymbolAddress((void**)&kraw, g_kraw);
    cudaGetSymbolAddress((void**)&att, g_att);
    cudaGetSymbolAddress((void**)&xh, g_xh);
    cudaGetSymbolAddress((void**)&vh, g_vh);
    cudaGetSymbolAddress((void**)&atth, g_atth);
    cudaGetSymbolAddress((void**)&rq, g_rq);
    cudaGetSymbolAddress((void**)&rk, g_rk);
    cudaGetSymbolAddress((void**)&wqh, g_wqh);
    cudaGetSymbolAddress((void**)&wkh, g_wkh);
    cudaGetSymbolAddress((void**)&wvh, g_wvh);
    cudaGetSymbolAddress((void**)&woh, g_woh);
    cudaGetSymbolAddress((void**)&mh, g_Mh);
    cudaGetSymbolAddress((void**)&zbuf, g_z);
    cudaGetSymbolAddress((void**)&mlbuf, g_ml);

    dim3 qkvGrid((S + 127) / 128, 36);
    dim3 gemmGrid((S + 127) / 128, DIM / 128);
    dim3 gatedGrid((S + 127) / 128, NH);
    dim3 attnGrid((S + 127) / 128, NH, 2);
    const int n4x = S * DIM / 4, n4w = DIM * DIM / 4;
    const float kscale = 0.08838834764831845f * 1.44269504088896341f;  // 128^-.5 * log2e

    conv_h<<<(n4x + 255) / 256, 256>>>(x, xh, n4x);
    conv_h<<<(n4w + 255) / 256, 256>>>(Wq, wqh, n4w);
    conv_h<<<(n4w + 255) / 256, 256>>>(Wk, wkh, n4w);
    conv_h<<<(n4w + 255) / 256, 256>>>(Wv, wvh, n4w);
    conv_h<<<(n4w + 255) / 256, 256>>>(Wo, woh, n4w);
    rope_table_k<<<S, 64>>>(freqs, hG, wG);
    gemm_qkv<<<qkvGrid, 256, GEMM_SMEM_BYTES>>>(xh, wqh, wkh, wvh, bq, bk, bv,
                                                qraw, kraw, vh, S);
    rmsrope_k<<<S, 384>>>(qraw, gq, g_kmean, rq, zbuf, 1, 1.0f);
    rmsrope_k<<<S, 384>>>(kraw, gk, g_kmean, rk, zbuf, 0, kscale);
    prepM_k<<<768, 256>>>(g_kv, Wlin);
    attn_f16<<<attnGrid, 256, ATT_SMEM_BYTES>>>(rq, rk, vh, qraw, kraw, mlbuf, S);
    combine_k<<<S, 384>>>(qraw, kraw, mlbuf, att, S);
    gatedmma_k<<<gatedGrid, 256, GATED_SMEM_BYTES>>>(rq, mh, blin, att, zbuf, atth, S);
    gemm_h<<<gemmGrid, 256, GEMM_SMEM_BYTES>>>(atth, woh, bo, out, S);
}